// round 6
// baseline (speedup 1.0000x reference)
#include <cuda_runtime.h>
#include <cstdint>

// ---------------- problem constants ----------------
#define IN_F   4096
#define OUT_F  4096
#define M_TOT  8192          // 4 * 2048 tokens

// GEMM tiling
#define BM 256
#define BN 128
#define BK 32
#define KTILES (IN_F / BK)   // 128
#define THREADS 512
#define STAGES 4

// device scratch (static __device__ arrays are allowed; no runtime alloc)
__device__ float g_W[(size_t)OUT_F * IN_F];   // W_eff = q*s + 2*(B@A), tf32-RN rounded (64 MB)
__device__ float g_X[(size_t)M_TOT * IN_F];   // x, tf32-RN rounded (128 MB)

// ---------------- helpers ----------------
__device__ __forceinline__ uint32_t smem_u32(const void* p) {
    uint32_t a;
    asm("{ .reg .u64 t; cvta.to.shared.u64 t, %1; cvt.u32.u64 %0, t; }" : "=r"(a) : "l"(p));
    return a;
}
__device__ __forceinline__ float to_tf32(float v) {
    uint32_t t;
    asm("cvt.rna.tf32.f32 %0, %1;" : "=r"(t) : "f"(v));
    return __uint_as_float(t);
}
__device__ __forceinline__ void cp16(uint32_t s, const void* g) {
    asm volatile("{ .reg .u64 ga; cvta.to.global.u64 ga, %1; cp.async.cg.shared.global [%0], [ga], 16; }"
                 :: "r"(s), "l"(g));
}
#define CP_COMMIT() asm volatile("cp.async.commit_group;" ::: "memory")
#define CP_WAIT(n)  asm volatile("cp.async.wait_group %0;" :: "n"(n) : "memory")

__device__ __forceinline__ void ldsm4(uint32_t* r, uint32_t a) {
    asm volatile("ldmatrix.sync.aligned.m8n8.x4.shared.b16 {%0,%1,%2,%3}, [%4];"
                 : "=r"(r[0]), "=r"(r[1]), "=r"(r[2]), "=r"(r[3]) : "r"(a));
}
__device__ __forceinline__ void mma1688(float* c, const uint32_t* a, const uint32_t* b) {
    asm volatile("mma.sync.aligned.m16n8k8.row.col.f32.tf32.tf32.f32 "
                 "{%0,%1,%2,%3}, {%4,%5,%6,%7}, {%8,%9}, {%0,%1,%2,%3};"
                 : "+f"(c[0]), "+f"(c[1]), "+f"(c[2]), "+f"(c[3])
                 : "r"(a[0]), "r"(a[1]), "r"(a[2]), "r"(a[3]), "r"(b[0]), "r"(b[1]));
}

// ---------------- stage 1a: W_eff = q*s + 2*(B@A), tf32-RN rounded ----------------
// grid: (OUT_F/16) * (IN_F/512) = 2048 blocks, 256 threads
__global__ void __launch_bounds__(256)
build_weff(const int* __restrict__ qw, const float* __restrict__ qs,
           const float* __restrict__ lA, const float* __restrict__ lB)
{
    __shared__ float sA[16 * 512];
    __shared__ float sB[16 * 16];
    __shared__ float sS[16];
    const int tid = threadIdx.x;
    const int o0 = (blockIdx.x >> 3) * 16;
    const int i0 = (blockIdx.x & 7) * 512;

    #pragma unroll
    for (int j = 0; j < 32; j++) {
        int idx = tid + 256 * j;
        sA[idx] = lA[(idx >> 9) * IN_F + i0 + (idx & 511)];
    }
    sB[tid & 255] = lB[(o0 + ((tid & 255) >> 4)) * 16 + (tid & 15)];
    if (tid < 16) sS[tid] = qs[o0 + tid];
    __syncthreads();

    #pragma unroll 4
    for (int j = 0; j < 32; j++) {
        int idx = tid + 256 * j;
        int ol = idx >> 9, ii = idx & 511;
        float acc = 0.f;
        #pragma unroll
        for (int r = 0; r < 16; r++) acc = fmaf(sB[ol * 16 + r], sA[r * 512 + ii], acc);
        size_t gidx = (size_t)(o0 + ol) * IN_F + i0 + ii;
        float w = fmaf((float)qw[gidx], sS[ol], 2.0f * acc);
        g_W[gidx] = to_tf32(w);
    }
}

// ---------------- stage 1b: round x to tf32-RN ----------------
__global__ void __launch_bounds__(256)
round_x(const float* __restrict__ x)
{
    size_t i = ((size_t)blockIdx.x * 256 + threadIdx.x) * 4;
    float4 v = *(const float4*)(x + i);
    v.x = to_tf32(v.x); v.y = to_tf32(v.y); v.z = to_tf32(v.z); v.w = to_tf32(v.w);
    *(float4*)(g_X + i) = v;
}

// ---------------- stage 2: mma.sync tf32 GEMM, 256x128 CTA tile ----------------
constexpr int A_BYTES     = BM * BK * 4;           // 32768
constexpr int B_BYTES     = BN * BK * 4;           // 16384
constexpr int STAGE_BYTES = A_BYTES + B_BYTES;     // 49152 (1024-aligned)
constexpr int SMEM_TOTAL  = STAGES * STAGE_BYTES;  // 196608

__device__ __forceinline__ void load_stage(uint32_t sb, int stage, int kt,
                                           int m0, int n0, int tid)
{
    const float* gx = g_X + (size_t)m0 * IN_F + kt * BK;
    const float* gw = g_W + (size_t)n0 * IN_F + kt * BK;
    const uint32_t sa = sb + stage * STAGE_BYTES;
    const uint32_t sbb = sa + A_BYTES;
    // A: 256 rows x 128B = 2048 x 16B chunks, 4 per thread
    #pragma unroll
    for (int q = 0; q < 4; q++) {
        int chunk = tid + THREADS * q;
        int row = chunk >> 3, c = chunk & 7;
        uint32_t so = sa + row * 128 + ((c * 16) ^ ((row & 7) * 16));
        cp16(so, gx + (size_t)row * IN_F + c * 4);
    }
    // B: 128 rows x 128B = 1024 x 16B chunks, 2 per thread
    #pragma unroll
    for (int q = 0; q < 2; q++) {
        int chunk = tid + THREADS * q;
        int row = chunk >> 3, c = chunk & 7;
        uint32_t so = sbb + row * 128 + ((c * 16) ^ ((row & 7) * 16));
        cp16(so, gw + (size_t)row * IN_F + c * 4);
    }
}

__global__ void __launch_bounds__(THREADS, 1)
gemm_mma(const float* __restrict__ bias, float* __restrict__ out)
{
    extern __shared__ __align__(1024) char smem[];
    const uint32_t sb = smem_u32(smem);
    const int tid = threadIdx.x, wid = tid >> 5, lane = tid & 31;
    const int m0 = (int)(blockIdx.x >> 5) * BM;   // n-fast ordering: W stays L2-resident
    const int n0 = (int)(blockIdx.x & 31) * BN;

    const int warp_m = (wid & 3) * 64;   // 4 warps along M
    const int warp_n = (wid >> 2) * 32;  // 4 warps along N

    // ldmatrix lane addressing (b16 trick: 8x4 f32 tile == 8x8 b16 tile)
    const int t = lane >> 3, r8 = lane & 7;
    // A fragment tiles: t0: rows+0..7,k0..3 | t1: rows+8..15,k0..3 | t2: +0..7,k4..7 | t3: +8..15,k4..7
    const uint32_t aRow128 = (uint32_t)(warp_m + r8 + (t & 1) * 8) * 128;
    const uint32_t aC = (uint32_t)(((t >> 1) * 16) ^ (r8 * 16));
    // B (n-major) tiles: t0: n0..7,k0..3 | t1: n0..7,k4..7 | t2: n8..15,k0..3 | t3: n8..15,k4..7
    const uint32_t bRow128 = (uint32_t)(warp_n + (t >> 1) * 8 + r8) * 128;
    const uint32_t bC = (uint32_t)(((t & 1) * 16) ^ (r8 * 16));

    float acc[4][4][4];
    #pragma unroll
    for (int a = 0; a < 4; a++)
        #pragma unroll
        for (int b = 0; b < 4; b++)
            #pragma unroll
            for (int c = 0; c < 4; c++) acc[a][b][c] = 0.f;

    // pipeline prologue: stages 0..STAGES-2
    #pragma unroll
    for (int s = 0; s < STAGES - 1; s++) {
        load_stage(sb, s, s, m0, n0, tid);
        CP_COMMIT();
    }

    #pragma unroll 1
    for (int kt = 0; kt < KTILES; kt++) {
        CP_WAIT(STAGES - 2);
        __syncthreads();

        // issue next stage first so cp.async overlaps the mma work
        if (kt + STAGES - 1 < KTILES)
            load_stage(sb, (kt + STAGES - 1) & (STAGES - 1), kt + STAGES - 1, m0, n0, tid);
        CP_COMMIT();

        const uint32_t sa = sb + (kt & (STAGES - 1)) * STAGE_BYTES;
        const uint32_t sB = sa + A_BYTES;

        #pragma unroll
        for (int ks = 0; ks < 4; ks++) {
            const uint32_t koff = (uint32_t)(ks << 5);
            uint32_t bf[2][4];
            ldsm4(bf[0], sB + bRow128 +        (koff ^ bC));
            ldsm4(bf[1], sB + bRow128 + 2048 + (koff ^ bC));
            #pragma unroll
            for (int mf = 0; mf < 4; mf++) {
                uint32_t af[4];
                ldsm4(af, sa + aRow128 + mf * 2048 + (koff ^ aC));
                #pragma unroll
                for (int i = 0; i < 2; i++) {
                    mma1688(acc[mf][2 * i],     af, &bf[i][0]);
                    mma1688(acc[mf][2 * i + 1], af, &bf[i][2]);
                }
            }
        }
    }

    // epilogue: c0/c1 -> (row, col..col+1), c2/c3 -> (row+8, col..col+1)
    const int row0 = m0 + warp_m + (lane >> 2);
    const int col0 = n0 + warp_n + (lane & 3) * 2;
    #pragma unroll
    for (int mf = 0; mf < 4; mf++) {
        #pragma unroll
        for (int nf = 0; nf < 4; nf++) {
            const int c = col0 + nf * 8;
            const float b0 = __ldg(bias + c), b1 = __ldg(bias + c + 1);
            const int rr = row0 + mf * 16;
            float2 v0 = { acc[mf][nf][0] + b0, acc[mf][nf][1] + b1 };
            float2 v1 = { acc[mf][nf][2] + b0, acc[mf][nf][3] + b1 };
            *(float2*)(out + (size_t)rr * OUT_F + c)       = v0;
            *(float2*)(out + (size_t)(rr + 8) * OUT_F + c) = v1;
        }
    }
}

// ---------------- launch ----------------
extern "C" void kernel_launch(void* const* d_in, const int* in_sizes, int n_in,
                              void* d_out, int out_size)
{
    const float* x    = (const float*)d_in[0];
    const int*   qw   = (const int*)  d_in[1];
    const float* qs   = (const float*)d_in[2];
    const float* bias = (const float*)d_in[3];
    const float* lA   = (const float*)d_in[4];
    const float* lB   = (const float*)d_in[5];
    float* out = (float*)d_out;

    cudaFuncSetAttribute(gemm_mma, cudaFuncAttributeMaxDynamicSharedMemorySize, SMEM_TOTAL);

    build_weff<<<(OUT_F / 16) * (IN_F / 512), 256>>>(qw, qs, lA, lB);
    round_x<<<(int)((size_t)M_TOT * IN_F / 4 / 256), 256>>>(x);
    gemm_mma<<<(M_TOT / BM) * (OUT_F / BN), THREADS, SMEM_TOTAL>>>(bias, out);
}